// round 3
// baseline (speedup 1.0000x reference)
#include <cuda_runtime.h>
#include <math.h>

#define Bb   2
#define CIN  64
#define HIDc 128
#define C2   256
#define DDim 32
#define HHe  56
#define WWi  56
#define HW   3136
#define PP   100352   // DDim*HW

// ---------------- scratch (static device allocations; harness-legal) ----------
__device__ float g_xz [Bb*(size_t)C2*PP];   // proj_in output (2*HID=256 ch)
__device__ float g_dw [Bb*(size_t)C2*PP];   // depthwise output (x1 = ch 0..127, x2 = ch 128..255)
__device__ float g_x1c[Bb*(size_t)HIDc*PP]; // relu(conv3d(x1))
__device__ float g_pool[Bb*HIDc*DDim];      // mean_{h,w} x2
__device__ float g_gate[Bb*HIDc*DDim];      // sigmoid gates

__device__ __forceinline__ float sigmoidf_(float x) { return 1.f / (1.f + expf(-x)); }

// ---------------- K1: proj_in  out[b,o,p] = sum_c inp[b,c,p]*W_in[o,c] -------
__global__ __launch_bounds__(256)
void k_proj(const float* __restrict__ inp, const float* __restrict__ W_in) {
    extern __shared__ float sw[];                    // 256*64 floats = 64KB
    int tid = threadIdx.x;
    for (int i = tid; i < C2*CIN; i += 256) sw[i] = W_in[i];
    __syncthreads();
    int b = blockIdx.y;
    int p = blockIdx.x * 256 + tid;
    float in[CIN];
#pragma unroll
    for (int c = 0; c < CIN; c++) in[c] = inp[(b*CIN + c)*PP + p];
    float* dst = g_xz + (size_t)b*C2*PP + p;
    for (int o = 0; o < C2; o++) {
        const float4* wr = (const float4*)(sw + o*CIN);
        float acc = 0.f;
#pragma unroll
        for (int q = 0; q < CIN/4; q++) {
            float4 w = wr[q];
            acc += in[4*q]*w.x + in[4*q+1]*w.y + in[4*q+2]*w.z + in[4*q+3]*w.w;
        }
        dst[(size_t)o*PP] = acc;
    }
}

// ---------------- K2: depthwise 3x3x3 (SAME) + fused H,W mean-pool of x2 -----
__global__ __launch_bounds__(256)
void k_dw(const float* __restrict__ W_dw) {
    __shared__ float s[3*58*58];
    __shared__ float red[256];
    int bid = blockIdx.x;
    int d = bid & 31;
    int c = (bid >> 5) & 255;
    int b = bid >> 13;
    int tid = threadIdx.x;
    const float* src = g_xz + ((size_t)(b*C2 + c))*PP;
    for (int idx = tid; idx < 3*58*58; idx += 256) {
        int ww = idx % 58; int t = idx / 58;
        int hh = t % 58;   int dd = t / 58;
        int gd = d + dd - 1, gh = hh - 1, gw = ww - 1;
        float v = 0.f;
        if ((unsigned)gd < DDim && (unsigned)gh < HHe && (unsigned)gw < WWi)
            v = src[gd*HW + gh*WWi + gw];
        s[idx] = v;
    }
    __syncthreads();
    float wv[27];
#pragma unroll
    for (int t = 0; t < 27; t++) wv[t] = W_dw[c*27 + t];
    float* dst = g_dw + ((size_t)(b*C2 + c))*PP + d*HW;
    float psum = 0.f;
    for (int idx = tid; idx < HW; idx += 256) {
        int h = idx / 56, w = idx % 56;
        float acc = 0.f;
#pragma unroll
        for (int kd = 0; kd < 3; kd++)
#pragma unroll
            for (int kh = 0; kh < 3; kh++)
#pragma unroll
                for (int kw = 0; kw < 3; kw++)
                    acc += s[(kd*58 + h+kh)*58 + (w+kw)] * wv[(kd*3+kh)*3 + kw];
        dst[idx] = acc;
        psum += acc;
    }
    if (c >= HIDc) {
        red[tid] = psum;
        __syncthreads();
        for (int off = 128; off > 0; off >>= 1) {
            if (tid < off) red[tid] += red[tid + off];
            __syncthreads();
        }
        if (tid == 0) g_pool[(b*HIDc + (c - HIDc))*DDim + d] = red[0] * (1.f/HW);
    }
}

// ---------------- K3: entire temporal branch (W_t1 -> Mamba -> W_t2 -> sigmoid)
// One block per batch (b=2). Scan state h[16] kept in registers (thread = d-channel).
__global__ __launch_bounds__(256)
void k_mamba(const float* __restrict__ W_t1, const float* __restrict__ W_t2,
             const float* __restrict__ in_w, const float* __restrict__ conv_w,
             const float* __restrict__ conv_b, const float* __restrict__ x_w,
             const float* __restrict__ dt_w, const float* __restrict__ dt_b,
             const float* __restrict__ A_log, const float* __restrict__ Dp,
             const float* __restrict__ out_w) {
    extern __shared__ float sm[];
    float* s_pool = sm;              // 128*32 = 4096
    float* s_seq  = sm + 4096;       // 32*128 = 4096   (reused as out_m)
    float* s_xr   = sm + 8192;       // 32*256 = 8192   (raw x; reused as y)
    float* s_x    = sm + 16384;      // 32*256
    float* s_z    = sm + 24576;      // 32*256
    float* s_dt   = sm + 32768;      // 32*256
    float* s_proj = sm + 40960;      // 32*40 = 1280
    int b = blockIdx.x, tid = threadIdx.x;

    for (int i = tid; i < HIDc*DDim; i += 256) s_pool[i] = g_pool[b*HIDc*DDim + i];
    __syncthreads();
    // seq[t][i] = sum_c W_t1[i][c] * pool[c][t]
    for (int idx = tid; idx < DDim*HIDc; idx += 256) {
        int t = idx >> 7, i = idx & 127;
        float a = 0.f;
        const float* w = W_t1 + i*HIDc;
        for (int c = 0; c < HIDc; c++) a += w[c] * s_pool[c*DDim + t];
        s_seq[t*HIDc + i] = a;
    }
    __syncthreads();
    // xz = seq @ in_w^T  (512 outputs: x raw / z)
    for (int idx = tid; idx < DDim*512; idx += 256) {
        int t = idx >> 9, j = idx & 511;
        float a = 0.f;
        const float* w = in_w + j*HIDc;
        const float* u = s_seq + t*HIDc;
        for (int i = 0; i < HIDc; i++) a += u[i]*w[i];
        if (j < 256) s_xr[t*256 + j] = a; else s_z[t*256 + (j-256)] = a;
    }
    __syncthreads();
    // causal depthwise conv1d (k=4) + silu
    for (int idx = tid; idx < DDim*256; idx += 256) {
        int t = idx >> 8, j = idx & 255;
        float a = conv_b[j];
#pragma unroll
        for (int k = 0; k < 4; k++) {
            int tt = t + k - 3;
            if (tt >= 0) a += s_xr[tt*256 + j] * conv_w[j*4 + k];
        }
        s_x[idx] = a * sigmoidf_(a);
    }
    __syncthreads();
    // x_proj -> (dt_raw | B | C)  (40 per step)
    for (int idx = tid; idx < DDim*40; idx += 256) {
        int t = idx / 40, q = idx % 40;
        float a = 0.f;
        const float* w = x_w + q*256;
        const float* u = s_x + t*256;
        for (int j = 0; j < 256; j++) a += u[j]*w[j];
        s_proj[idx] = a;
    }
    __syncthreads();
    // dt = softplus(dt_raw @ dt_w^T + b)
    for (int idx = tid; idx < DDim*256; idx += 256) {
        int t = idx >> 8, j = idx & 255;
        float a = dt_b[j];
#pragma unroll
        for (int r = 0; r < 8; r++) a += s_proj[t*40 + r]*dt_w[j*8 + r];
        s_dt[idx] = (a > 20.f) ? a : log1pf(expf(a));
    }
    __syncthreads();
    // selective scan: thread tid owns channel d, state in registers
    {
        int dch = tid;
        float A[16], h[16];
#pragma unroll
        for (int n = 0; n < 16; n++) { A[n] = -expf(A_log[dch*16 + n]); h[n] = 0.f; }
        float Dv = Dp[dch];
        for (int t = 0; t < DDim; t++) {
            float dtv = s_dt[t*256 + dch];
            float xv  = s_x [t*256 + dch];
            float y = 0.f;
#pragma unroll
            for (int n = 0; n < 16; n++) {
                float dA = expf(dtv * A[n]);
                h[n] = dA*h[n] + dtv * s_proj[t*40 + 8 + n] * xv;
                y += h[n] * s_proj[t*40 + 24 + n];
            }
            y += xv * Dv;
            float zv = s_z[t*256 + dch];
            y *= zv * sigmoidf_(zv);
            s_xr[t*256 + dch] = y;              // reuse s_xr as y
        }
    }
    __syncthreads();
    // out_m = y @ out_w^T  (128)
    for (int idx = tid; idx < DDim*HIDc; idx += 256) {
        int t = idx >> 7, o = idx & 127;
        float a = 0.f;
        const float* w = out_w + o*256;
        const float* u = s_xr + t*256;
        for (int j = 0; j < 256; j++) a += u[j]*w[j];
        s_seq[idx] = a;                         // reuse s_seq as out_m
    }
    __syncthreads();
    // gate = sigmoid(W_t2 @ out_m)
    for (int idx = tid; idx < DDim*HIDc; idx += 256) {
        int t = idx >> 7, o = idx & 127;
        float a = 0.f;
        const float* w = W_t2 + o*HIDc;
        const float* u = s_seq + t*HIDc;
        for (int c = 0; c < HIDc; c++) a += u[c]*w[c];
        g_gate[(b*HIDc + o)*DDim + t] = sigmoidf_(a);
    }
}

// ---------------- K4: dense 3x3x3 conv 128->128 + ReLU (the hot kernel) ------
// Block: (b, d, 4-row h-tile, 32-out-channel chunk). 256 thr = 8 o-groups x 32 pos-groups.
// Thread: 4 out-ch x 7 w-positions = 28 accums. smem: input (pad 72 -> conflict-free
// across hrow lanes) + weights [c][tap][o] pad 36 (16B-aligned float4, warp-broadcast).
#define IST 72
#define WST 36
__global__ __launch_bounds__(256)
void k_conv(const float* __restrict__ Ws) {
    extern __shared__ float smc[];
    float* sIn = smc;                   // 8*3*6*IST = 10368 floats
    float* sW  = smc + 8*3*6*IST;       // 8*27*WST  = 7776 floats
    int bid = blockIdx.x;
    int oc = bid & 3;
    int rest = bid >> 2;
    int ht = rest % 14;
    int d  = (rest / 14) % 32;
    int b  = rest / (14*32);
    int o0 = oc*32, h0 = ht*4;
    int tid = threadIdx.x;
    int og = tid >> 5, pg = tid & 31;
    int hrow = pg >> 3, wg = pg & 7, w0 = wg*7;
    float acc[4][7];
#pragma unroll
    for (int a = 0; a < 4; a++)
#pragma unroll
        for (int i = 0; i < 7; i++) acc[a][i] = 0.f;

    const float* src = g_dw + (size_t)b*C2*PP;   // x1 = channels 0..127
    for (int cc = 0; cc < 16; cc++) {
        int c0 = cc*8;
        for (int idx = tid; idx < 8*3*6*58; idx += 256) {
            int ww = idx % 58; int t = idx / 58;
            int hh = t % 6; t /= 6;
            int dd = t % 3; int cl = t / 3;
            int gd = d + dd - 1, gh = h0 + hh - 1, gw = ww - 1;
            float v = 0.f;
            if ((unsigned)gd < DDim && (unsigned)gh < HHe && (unsigned)gw < WWi)
                v = src[(size_t)(c0+cl)*PP + gd*HW + gh*WWi + gw];
            sIn[((cl*3+dd)*6 + hh)*IST + ww] = v;
        }
        for (int idx = tid; idx < 32*8*27; idx += 256) {
            int tap = idx % 27; int t = idx / 27;
            int cl = t % 8; int ol = t / 8;
            sW[(cl*27 + tap)*WST + ol] = Ws[((size_t)(o0+ol)*HIDc + (c0+cl))*27 + tap];
        }
        __syncthreads();
#pragma unroll 1
        for (int cl = 0; cl < 8; cl++) {
#pragma unroll
            for (int kd = 0; kd < 3; kd++) {
#pragma unroll
                for (int kh = 0; kh < 3; kh++) {
                    const float* row = sIn + ((cl*3+kd)*6 + hrow + kh)*IST + w0;
                    float r[9];
#pragma unroll
                    for (int j = 0; j < 9; j++) r[j] = row[j];
                    const float* wp = sW + (cl*27 + (kd*3+kh)*3)*WST + og*4;
#pragma unroll
                    for (int kw = 0; kw < 3; kw++) {
                        float4 w = *(const float4*)(wp + kw*WST);
#pragma unroll
                        for (int i = 0; i < 7; i++) {
                            float x = r[i+kw];
                            acc[0][i] += w.x*x;
                            acc[1][i] += w.y*x;
                            acc[2][i] += w.z*x;
                            acc[3][i] += w.w*x;
                        }
                    }
                }
            }
        }
        __syncthreads();
    }
    int h = h0 + hrow;
    float* dst = g_x1c + (size_t)b*HIDc*PP + (size_t)d*HW + h*WWi + w0;
#pragma unroll
    for (int oo = 0; oo < 4; oo++) {
        int o = o0 + og*4 + oo;
#pragma unroll
        for (int i = 0; i < 7; i++)
            dst[(size_t)o*PP + i] = fmaxf(acc[oo][i], 0.f);
    }
}

// ---------------- K5: out[b,o,p] = sum_c x1c[b,c,p]*gate[b,c,d(p)]*W_out[o,c] -
__global__ __launch_bounds__(256)
void k_final(const float* __restrict__ W_out, float* __restrict__ out) {
    __shared__ float sw[HIDc*64];                 // transposed: sw[c*64+o]
    int tid = threadIdx.x;
    for (int i = tid; i < HIDc*64; i += 256) {
        int c = i >> 6, o = i & 63;
        sw[i] = W_out[o*HIDc + c];
    }
    __syncthreads();
    int b = blockIdx.y;
    int p = blockIdx.x*256 + tid;
    int d = p / HW;
    float acc[64];
#pragma unroll
    for (int o = 0; o < 64; o++) acc[o] = 0.f;
    const float* src  = g_x1c + (size_t)b*HIDc*PP + p;
    const float* gate = g_gate + b*HIDc*DDim + d;
    for (int c = 0; c < HIDc; c++) {
        float v = src[(size_t)c*PP] * gate[c*DDim];
        const float4* wr = (const float4*)(sw + c*64);
#pragma unroll
        for (int q = 0; q < 16; q++) {
            float4 w = wr[q];
            acc[4*q]   += v*w.x;
            acc[4*q+1] += v*w.y;
            acc[4*q+2] += v*w.z;
            acc[4*q+3] += v*w.w;
        }
    }
    float* dst = out + (size_t)b*64*PP + p;
#pragma unroll
    for (int o = 0; o < 64; o++) dst[(size_t)o*PP] = acc[o];
}

// ---------------- launch ------------------------------------------------------
extern "C" void kernel_launch(void* const* d_in, const int* in_sizes, int n_in,
                              void* d_out, int out_size) {
    const float* inp      = (const float*)d_in[0];
    const float* W_in     = (const float*)d_in[1];
    const float* W_dw     = (const float*)d_in[2];
    const float* W_s      = (const float*)d_in[3];
    const float* W_t1     = (const float*)d_in[4];
    const float* W_t2     = (const float*)d_in[5];
    const float* m_in_w   = (const float*)d_in[6];
    const float* m_conv_w = (const float*)d_in[7];
    const float* m_conv_b = (const float*)d_in[8];
    const float* m_x_w    = (const float*)d_in[9];
    const float* m_dt_w   = (const float*)d_in[10];
    const float* m_dt_b   = (const float*)d_in[11];
    const float* m_A_log  = (const float*)d_in[12];
    const float* m_D      = (const float*)d_in[13];
    const float* m_out_w  = (const float*)d_in[14];
    const float* W_out    = (const float*)d_in[15];
    float* out = (float*)d_out;

    cudaFuncSetAttribute(k_proj,  cudaFuncAttributeMaxDynamicSharedMemorySize, C2*CIN*4);
    cudaFuncSetAttribute(k_mamba, cudaFuncAttributeMaxDynamicSharedMemorySize, 42240*4);
    cudaFuncSetAttribute(k_conv,  cudaFuncAttributeMaxDynamicSharedMemorySize, (8*3*6*IST + 8*27*WST)*4);

    k_proj <<<dim3(PP/256, Bb), 256, C2*CIN*4>>>(inp, W_in);
    k_dw   <<<Bb*C2*DDim, 256>>>(W_dw);
    k_mamba<<<Bb, 256, 42240*4>>>(W_t1, W_t2, m_in_w, m_conv_w, m_conv_b,
                                  m_x_w, m_dt_w, m_dt_b, m_A_log, m_D, m_out_w);
    k_conv <<<Bb*DDim*14*4, 256, (8*3*6*IST + 8*27*WST)*4>>>(W_s);
    k_final<<<dim3(PP/256, Bb), 256>>>(W_out, out);
}